// round 14
// baseline (speedup 1.0000x reference)
#include <cuda_runtime.h>
#include <math.h>
#include <stdint.h>

#define BB 16
#define SS 1024
#define NB 64
#define NSTEP 16   // 1024/64

// ---- static device scratch (allocation-free) ----
static __device__ float g_M [(size_t)BB * SS * SS];          // 64 MB: minors -> inverses
static __device__ float g_S [(size_t)BB * 16 * 16 * 4096];   // 67 MB: stash slots [b][k][jb][64x64]
static __device__ float g_P [(size_t)BB * 16 * 4096];        // 4 MB: pivot-inverse slots [b][k]
static __device__ unsigned long long g_maxkey;               // (sortable-key<<32)|argmax
static __device__ int g_V [BB * 256];                        // tile version counters [b][i][j]
static __device__ int g_Pf[BB];                              // pivot slot validity: slot g_Pf[b] ready

__device__ __forceinline__ unsigned int enc_f(float v) {
    unsigned int u = __float_as_uint(v);
    return (u & 0x80000000u) ? ~u : (u | 0x80000000u);
}
__device__ __forceinline__ float dec_f(unsigned int k) {
    unsigned int u = (k & 0x80000000u) ? (k ^ 0x80000000u) : ~k;
    return __uint_as_float(u);
}
__device__ __forceinline__ float get_m() { return dec_f((unsigned int)(g_maxkey >> 32)); }

// ---- register Gauss-Jordan inversion of a 64x64 block (8 warps x 8 rows x 2 cols/lane) ----
__device__ __forceinline__ void gj64(float pr[8][2], float (*rowbuf)[64], int w, int l) {
    for (int pw = 0; pw < 8; pw++) {
        #pragma unroll
        for (int rp = 0; rp < 8; rp++) {
            const int p = pw * 8 + rp;
            float* buf = rowbuf[rp & 1];
            if (w == pw) { buf[l] = pr[rp][0]; buf[l + 32] = pr[rp][1]; }
            __syncthreads();
            const float r0 = buf[l], r1 = buf[l + 32];
            const float pinv = 1.0f / buf[p];
            const bool hi = (p >= 32);
            const int pl = p & 31;
            #pragma unroll
            for (int r = 0; r < 8; r++) {
                const float src = hi ? pr[r][1] : pr[r][0];
                const float colv = __shfl_sync(0xffffffffu, src, pl);
                if (r == rp && w == pw) {
                    pr[r][0] = r0 * pinv;
                    pr[r][1] = r1 * pinv;
                    if (l == pl) { if (hi) pr[r][1] = pinv; else pr[r][0] = pinv; }
                } else {
                    const float sc = colv * pinv;
                    pr[r][0] -= sc * r0;
                    pr[r][1] -= sc * r1;
                    if (l == pl) { if (hi) pr[r][1] = -sc; else pr[r][0] = -sc; }
                }
            }
        }
    }
}

// ---------------- global max + argmax (float4 loads) ----------------
__global__ void k_max(const float* __restrict__ s) {
    __shared__ unsigned long long sm[256];
    unsigned long long best = 0ULL;
    const size_t total4 = (size_t)BB * SS * SS / 4;
    for (size_t i = (size_t)blockIdx.x * blockDim.x + threadIdx.x; i < total4;
         i += (size_t)gridDim.x * blockDim.x) {
        const float4 v = *((const float4*)s + i);
        const unsigned int i4 = (unsigned int)(i << 2);
        unsigned long long c0 = ((unsigned long long)enc_f(v.x) << 32) | (i4 + 0);
        unsigned long long c1 = ((unsigned long long)enc_f(v.y) << 32) | (i4 + 1);
        unsigned long long c2 = ((unsigned long long)enc_f(v.z) << 32) | (i4 + 2);
        unsigned long long c3 = ((unsigned long long)enc_f(v.w) << 32) | (i4 + 3);
        if (c1 > c0) c0 = c1;
        if (c3 > c2) c2 = c3;
        if (c2 > c0) c0 = c2;
        if (c0 > best) best = c0;
    }
    sm[threadIdx.x] = best;
    __syncthreads();
    for (int o = 128; o > 0; o >>= 1) {
        if (threadIdx.x < o && sm[threadIdx.x + o] > sm[threadIdx.x]) sm[threadIdx.x] = sm[threadIdx.x + o];
        __syncthreads();
    }
    if (threadIdx.x == 0) atomicMax(&g_maxkey, sm[0]);
}

// ---------------- fused rowsum + build: one block per M row ----------------
__global__ void __launch_bounds__(256) k_build2(const float* __restrict__ s) {
    __shared__ float e[1024];
    __shared__ double sd[256];
    const int p = blockIdx.x;            // 0..1023
    const int b = blockIdx.y;
    const int tid = threadIdx.x;
    float* Mrow = g_M + ((size_t)b << 20) + ((size_t)p << 10);

    if (p == 1023) {
        for (int q = tid; q < 1024; q += 256) Mrow[q] = (q == 1023) ? 1.0f : 0.0f;
        return;
    }
    const float m = get_m();
    const float* srow = s + ((size_t)b << 20) + ((size_t)(p + 1) << 10);
    float4 v = *(const float4*)(srow + tid * 4);
    float e0 = expf(v.x - m), e1 = expf(v.y - m), e2 = expf(v.z - m), e3 = expf(v.w - m);
    e[tid * 4 + 0] = e0; e[tid * 4 + 1] = e1; e[tid * 4 + 2] = e2; e[tid * 4 + 3] = e3;
    sd[tid] = (double)e0 + (double)e1 + (double)e2 + (double)e3;
    __syncthreads();
    for (int o = 128; o > 0; o >>= 1) {
        if (tid < o) sd[tid] += sd[tid + o];
        __syncthreads();
    }
    const double r = sd[0];
    for (int q = tid; q < 1024; q += 256) {
        float out;
        if (q == 1023)      out = 0.0f;
        else if (q == p)    out = (float)(r - (double)e[p + 1]);
        else                out = -e[q + 1];
        Mrow[q] = out;
    }
}

// ---------------- initial pivot inversion + flag reset ----------------
__global__ void __launch_bounds__(256) k_inv0() {
    __shared__ float rowbuf[2][64];
    const int b = blockIdx.x, tid = threadIdx.x;
    const int w = tid >> 5, l = tid & 31;
    g_V[b * 256 + tid] = 0;                 // reset all 256 tile versions of this batch
    if (tid == 0) g_Pf[b] = 0;              // slot 0 becomes valid at end of this launch
    float pr[8][2];
    const float* Pg = g_M + ((size_t)b << 20);
    #pragma unroll
    for (int r = 0; r < 8; r++) {
        pr[r][0] = Pg[((size_t)(w * 8 + r) << 10) + l];
        pr[r][1] = Pg[((size_t)(w * 8 + r) << 10) + l + 32];
    }
    gj64(pr, rowbuf, w, l);
    float* Pd = g_P + ((size_t)(b * 16) << 12);   // slot 0
    #pragma unroll
    for (int r = 0; r < 8; r++) {
        Pd[(w * 8 + r) * NB + l]      = pr[r][0];
        Pd[(w * 8 + r) * NB + l + 32] = pr[r][1];
    }
}

// =====================================================================
// Whole-factorization kernel: ONE launch, grid 16*4080 (step-major).
// Within a step: bids 0..479 panels (batch-interleaved), 480.. trail.
// All ordering via per-tile version counters g_V (value k+1 after step-k
// update) and pivot-slot flag g_Pf. tid0 spins; syncthreads+threadfence
// is the acquire; threadfence+syncthreads before flag-set is the release.
// =====================================================================
__global__ void __launch_bounds__(256) k_all() {
    __shared__ float AsT[2][32 * 68];
    __shared__ float Bs [2][32 * 68];
    __shared__ float rowbuf[2][64];
    const int tid = threadIdx.x;
    const int k   = blockIdx.x / 4080;
    const int sub = blockIdx.x % 4080;

    if (sub < 480) {
        // ================= PANEL ROLE =================
        const int b = sub & 15;
        const int x = sub >> 4;               // 0..29
        const size_t base = (size_t)b << 20;
        const int role = (x < 15) ? 0 : 1;
        const float* Pd = g_P + ((size_t)(b * 16 + k) << 12);

        int ib = k, jb = k;
        if (role == 0) jb = x + (x >= k);
        else           ib = (x - 15) + ((x - 15) >= k);
        const int tile_i = (role == 0) ? k : ib;
        const int tile_j = (role == 0) ? jb : k;

        // ---- gate: operand tile at version k, pivot slot k ready ----
        if (tid == 0) {
            volatile int* vT = &g_V[b * 256 + tile_i * 16 + tile_j];
            volatile int* pf = &g_Pf[b];
            while (*vT < k || *pf < k) __nanosleep(32);
        }
        __syncthreads();
        __threadfence();

        const int ai0 = tid >> 3, ac = (tid & 7) << 2;
        const int ai1 = ai0 + 32;
        const int bk0 = tid >> 4, bj = (tid & 15) << 2;
        const int bk1 = bk0 + 16;

        const float* Ag;
        const float* Bg;
        float* Sg = 0;
        int bstride;
        if (role == 0) {
            Ag = Pd;
            Bg = g_M + base + (((size_t)k * NB) << 10) + (size_t)jb * NB;
            Sg = g_S + ((size_t)((b * 16 + k) * 16 + jb) << 12);
            bstride = 1024;
        } else {
            Ag = g_M + base + (((size_t)ib * NB) << 10) + (size_t)k * NB;
            Bg = Pd;
            bstride = NB;
        }
        const int astride = (role == 0) ? NB : 1024;

        float4 A0 = *(const float4*)(Ag + (size_t)ai0 * astride + ac);
        float4 A1 = *(const float4*)(Ag + (size_t)ai1 * astride + ac);
        float4 B0 = *(const float4*)(Bg + (size_t)bk0 * bstride + bj);
        float4 B1 = *(const float4*)(Bg + (size_t)bk1 * bstride + bj);
        AsT[0][(ac + 0) * 68 + ai0] = A0.x; AsT[0][(ac + 1) * 68 + ai0] = A0.y;
        AsT[0][(ac + 2) * 68 + ai0] = A0.z; AsT[0][(ac + 3) * 68 + ai0] = A0.w;
        AsT[0][(ac + 0) * 68 + ai1] = A1.x; AsT[0][(ac + 1) * 68 + ai1] = A1.y;
        AsT[0][(ac + 2) * 68 + ai1] = A1.z; AsT[0][(ac + 3) * 68 + ai1] = A1.w;
        *(float4*)(&Bs[0][bk0 * 68 + bj]) = B0;
        *(float4*)(&Bs[0][bk1 * 68 + bj]) = B1;
        if (role == 0) {
            *(float4*)(Sg + bk0 * NB + bj) = B0;
            *(float4*)(Sg + bk1 * NB + bj) = B1;
        }
        A0 = *(const float4*)(Ag + (size_t)ai0 * astride + 32 + ac);
        A1 = *(const float4*)(Ag + (size_t)ai1 * astride + 32 + ac);
        B0 = *(const float4*)(Bg + (size_t)(bk0 + 32) * bstride + bj);
        B1 = *(const float4*)(Bg + (size_t)(bk1 + 32) * bstride + bj);
        __syncthreads();

        const int j0 = (tid & 15) * 4;
        const int i0 = (tid >> 4) * 4;
        float acc[4][4] = {};
        #pragma unroll 8
        for (int kk = 0; kk < 32; kk++) {
            const float4 a = *(const float4*)(&AsT[0][kk * 68 + i0]);
            const float4 v = *(const float4*)(&Bs [0][kk * 68 + j0]);
            acc[0][0] += a.x * v.x; acc[0][1] += a.x * v.y; acc[0][2] += a.x * v.z; acc[0][3] += a.x * v.w;
            acc[1][0] += a.y * v.x; acc[1][1] += a.y * v.y; acc[1][2] += a.y * v.z; acc[1][3] += a.y * v.w;
            acc[2][0] += a.z * v.x; acc[2][1] += a.z * v.y; acc[2][2] += a.z * v.z; acc[2][3] += a.z * v.w;
            acc[3][0] += a.w * v.x; acc[3][1] += a.w * v.y; acc[3][2] += a.w * v.z; acc[3][3] += a.w * v.w;
        }
        AsT[1][(ac + 0) * 68 + ai0] = A0.x; AsT[1][(ac + 1) * 68 + ai0] = A0.y;
        AsT[1][(ac + 2) * 68 + ai0] = A0.z; AsT[1][(ac + 3) * 68 + ai0] = A0.w;
        AsT[1][(ac + 0) * 68 + ai1] = A1.x; AsT[1][(ac + 1) * 68 + ai1] = A1.y;
        AsT[1][(ac + 2) * 68 + ai1] = A1.z; AsT[1][(ac + 3) * 68 + ai1] = A1.w;
        *(float4*)(&Bs[1][bk0 * 68 + bj]) = B0;
        *(float4*)(&Bs[1][bk1 * 68 + bj]) = B1;
        if (role == 0) {
            *(float4*)(Sg + (bk0 + 32) * NB + bj) = B0;
            *(float4*)(Sg + (bk1 + 32) * NB + bj) = B1;
        }
        __syncthreads();
        #pragma unroll 8
        for (int kk = 0; kk < 32; kk++) {
            const float4 a = *(const float4*)(&AsT[1][kk * 68 + i0]);
            const float4 v = *(const float4*)(&Bs [1][kk * 68 + j0]);
            acc[0][0] += a.x * v.x; acc[0][1] += a.x * v.y; acc[0][2] += a.x * v.z; acc[0][3] += a.x * v.w;
            acc[1][0] += a.y * v.x; acc[1][1] += a.y * v.y; acc[1][2] += a.y * v.z; acc[1][3] += a.y * v.w;
            acc[2][0] += a.z * v.x; acc[2][1] += a.z * v.y; acc[2][2] += a.z * v.z; acc[2][3] += a.z * v.w;
            acc[3][0] += a.w * v.x; acc[3][1] += a.w * v.y; acc[3][2] += a.w * v.z; acc[3][3] += a.w * v.w;
        }

        float* Cg = g_M + base + (((size_t)tile_i * NB) << 10) + (size_t)tile_j * NB;
        const float sgn = (role == 0) ? 1.0f : -1.0f;
        #pragma unroll
        for (int r = 0; r < 4; r++) {
            float4 c;
            c.x = sgn * acc[r][0]; c.y = sgn * acc[r][1];
            c.z = sgn * acc[r][2]; c.w = sgn * acc[r][3];
            *(float4*)(Cg + ((size_t)(i0 + r) << 10) + j0) = c;
        }

        // ---- release ----
        __threadfence();
        __syncthreads();
        if (tid == 0) atomicExch(&g_V[b * 256 + tile_i * 16 + tile_j], k + 1);
        return;
    }

    // ================= TRAIL ROLE =================
    const int t = sub - 480;
    const int b = t & 15;
    const int u = t >> 4;                 // 0..224
    const int ib = (k + 1 + u / 15) & 15;
    const int jb = (k + 1 + u % 15) & 15;
    const bool special = (u == 0);
    const size_t base = (size_t)b << 20;
    const int w = tid >> 5, l = tid & 31;

    if (special) {
        // gate: tile (k,k) at version k (trail(k-1) done) and pivot slot k ready
        if (tid == 0) {
            volatile int* vKK = &g_V[b * 256 + k * 16 + k];
            volatile int* pf  = &g_Pf[b];
            while (*vKK < k || *pf < k) __nanosleep(32);
        }
        __syncthreads();
        __threadfence();
        const float* Pd = g_P + ((size_t)(b * 16 + k) << 12);
        float* Pg = g_M + base + (((size_t)k * NB) << 10) + (size_t)k * NB;
        #pragma unroll
        for (int f = tid; f < 1024; f += 256) {
            const int r = f >> 4, c4 = (f & 15) << 2;
            *(float4*)(Pg + ((size_t)r << 10) + c4) = *(const float4*)(Pd + r * NB + c4);
        }
        __threadfence();   // install visible before V[k][k] is tagged below
    }

    // ---- gate: both panels done (v=k+1) and own C tile at version k ----
    if (tid == 0) {
        volatile int* vR = &g_V[b * 256 + k  * 16 + jb];
        volatile int* vC = &g_V[b * 256 + ib * 16 + k ];
        volatile int* vO = &g_V[b * 256 + ib * 16 + jb];
        const int want = k + 1;
        while (*vR < want || *vC < want || *vO < k) __nanosleep(32);
    }
    __syncthreads();
    __threadfence();

    const float* Ag = g_M + base + (((size_t)ib * NB) << 10) + (size_t)k * NB;   // L_new(ib,k)
    const float* Bg = g_S + ((size_t)((b * 16 + k) * 16 + jb) << 12);            // stash slot

    const int ai0 = tid >> 3, ac = (tid & 7) << 2;
    const int ai1 = ai0 + 32;
    const int bk0 = tid >> 4, bj = (tid & 15) << 2;
    const int bk1 = bk0 + 16;

    float4 A0 = *(const float4*)(Ag + ((size_t)ai0 << 10) + ac);
    float4 A1 = *(const float4*)(Ag + ((size_t)ai1 << 10) + ac);
    float4 B0 = *(const float4*)(Bg + bk0 * NB + bj);
    float4 B1 = *(const float4*)(Bg + bk1 * NB + bj);
    AsT[0][(ac + 0) * 68 + ai0] = A0.x; AsT[0][(ac + 1) * 68 + ai0] = A0.y;
    AsT[0][(ac + 2) * 68 + ai0] = A0.z; AsT[0][(ac + 3) * 68 + ai0] = A0.w;
    AsT[0][(ac + 0) * 68 + ai1] = A1.x; AsT[0][(ac + 1) * 68 + ai1] = A1.y;
    AsT[0][(ac + 2) * 68 + ai1] = A1.z; AsT[0][(ac + 3) * 68 + ai1] = A1.w;
    *(float4*)(&Bs[0][bk0 * 68 + bj]) = B0;
    *(float4*)(&Bs[0][bk1 * 68 + bj]) = B1;
    A0 = *(const float4*)(Ag + ((size_t)ai0 << 10) + 32 + ac);
    A1 = *(const float4*)(Ag + ((size_t)ai1 << 10) + 32 + ac);
    B0 = *(const float4*)(Bg + (bk0 + 32) * NB + bj);
    B1 = *(const float4*)(Bg + (bk1 + 32) * NB + bj);
    __syncthreads();

    const int j0 = (tid & 15) * 4;
    const int i0 = (tid >> 4) * 4;
    float acc[4][4] = {};
    #pragma unroll 8
    for (int kk = 0; kk < 32; kk++) {
        const float4 a = *(const float4*)(&AsT[0][kk * 68 + i0]);
        const float4 v = *(const float4*)(&Bs [0][kk * 68 + j0]);
        acc[0][0] += a.x * v.x; acc[0][1] += a.x * v.y; acc[0][2] += a.x * v.z; acc[0][3] += a.x * v.w;
        acc[1][0] += a.y * v.x; acc[1][1] += a.y * v.y; acc[1][2] += a.y * v.z; acc[1][3] += a.y * v.w;
        acc[2][0] += a.z * v.x; acc[2][1] += a.z * v.y; acc[2][2] += a.z * v.z; acc[2][3] += a.z * v.w;
        acc[3][0] += a.w * v.x; acc[3][1] += a.w * v.y; acc[3][2] += a.w * v.z; acc[3][3] += a.w * v.w;
    }
    AsT[1][(ac + 0) * 68 + ai0] = A0.x; AsT[1][(ac + 1) * 68 + ai0] = A0.y;
    AsT[1][(ac + 2) * 68 + ai0] = A0.z; AsT[1][(ac + 3) * 68 + ai0] = A0.w;
    AsT[1][(ac + 0) * 68 + ai1] = A1.x; AsT[1][(ac + 1) * 68 + ai1] = A1.y;
    AsT[1][(ac + 2) * 68 + ai1] = A1.z; AsT[1][(ac + 3) * 68 + ai1] = A1.w;
    *(float4*)(&Bs[1][bk0 * 68 + bj]) = B0;
    *(float4*)(&Bs[1][bk1 * 68 + bj]) = B1;
    __syncthreads();
    #pragma unroll 8
    for (int kk = 0; kk < 32; kk++) {
        const float4 a = *(const float4*)(&AsT[1][kk * 68 + i0]);
        const float4 v = *(const float4*)(&Bs [1][kk * 68 + j0]);
        acc[0][0] += a.x * v.x; acc[0][1] += a.x * v.y; acc[0][2] += a.x * v.z; acc[0][3] += a.x * v.w;
        acc[1][0] += a.y * v.x; acc[1][1] += a.y * v.y; acc[1][2] += a.y * v.z; acc[1][3] += a.y * v.w;
        acc[2][0] += a.z * v.x; acc[2][1] += a.z * v.y; acc[2][2] += a.z * v.z; acc[2][3] += a.z * v.w;
        acc[3][0] += a.w * v.x; acc[3][1] += a.w * v.y; acc[3][2] += a.w * v.z; acc[3][3] += a.w * v.w;
    }

    float* Cg = g_M + base + (((size_t)ib * NB) << 10) + (size_t)jb * NB;
    #pragma unroll
    for (int r = 0; r < 4; r++) {
        float4 c = *(float4*)(Cg + ((size_t)(i0 + r) << 10) + j0);
        c.x += acc[r][0]; c.y += acc[r][1]; c.z += acc[r][2]; c.w += acc[r][3];
        *(float4*)(Cg + ((size_t)(i0 + r) << 10) + j0) = c;
    }

    // ---- release: C update (and install, if special) visible, tag versions ----
    __threadfence();
    __syncthreads();
    if (tid == 0) {
        atomicExch(&g_V[b * 256 + ib * 16 + jb], k + 1);
        if (special) atomicExch(&g_V[b * 256 + k * 16 + k], k + 1);
    }

    // ---- fused next-pivot inversion: tile (k+1,k+1) just written by this CTA ----
    if (special && k < NSTEP - 1) {
        const int kn = (k + 1) & 15;
        const float* Pg = g_M + base + (((size_t)kn * NB) << 10) + (size_t)kn * NB;
        float pr[8][2];
        #pragma unroll
        for (int r = 0; r < 8; r++) {
            pr[r][0] = Pg[((size_t)(w * 8 + r) << 10) + l];
            pr[r][1] = Pg[((size_t)(w * 8 + r) << 10) + l + 32];
        }
        gj64(pr, rowbuf, w, l);
        float* Pd = g_P + ((size_t)(b * 16 + k + 1) << 12);
        #pragma unroll
        for (int r = 0; r < 8; r++) {
            Pd[(w * 8 + r) * NB + l]      = pr[r][0];
            Pd[(w * 8 + r) * NB + l + 32] = pr[r][1];
        }
        __threadfence();
        __syncthreads();
        if (tid == 0) atomicExch(&g_Pf[b], k + 1);
    }
}

// ---------------- assemble probs (fused transpose + fused diag read) ----------------
__global__ void k_out2(const float* __restrict__ s, float* __restrict__ out) {
    __shared__ float tile[32][33];
    __shared__ float sdiag[32];
    const int b  = blockIdx.z;
    const int p0 = blockIdx.y * 32;
    const int q0 = blockIdx.x * 32;
    const int tx = threadIdx.x, ty = threadIdx.y;   // 32 x 8
    const size_t base = (size_t)b << 20;

    for (int r = ty; r < 32; r += 8) {
        const int q = q0 + r, p = p0 + tx;
        float v = 0.0f;
        if (q >= 1 && p >= 1) v = g_M[base + ((size_t)(q - 1) << 10) + (p - 1)];
        tile[r][tx] = v;
    }
    if (ty == 0) {
        const int p = p0 + tx;
        sdiag[tx] = (p >= 1) ? g_M[base + (size_t)(p - 1) * 1025] : 0.0f;
    }
    __syncthreads();

    const float m = get_m();
    const unsigned long long key = g_maxkey;
    const unsigned int amax = (unsigned int)(key & 0xffffffffu);
    for (int r = ty; r < 32; r += 8) {
        const int p = p0 + r, q = q0 + tx;
        const size_t t = base + ((size_t)p << 10) + q;
        float v = 0.0f;
        if (p >= 1) {
            const float sub = (q >= 1) ? tile[tx][r] : 0.0f;
            v = expf(s[t] - m) * (sdiag[r] - sub);
        }
        if ((unsigned int)t == amax) v += 16.0f;
        out[t] = v;
    }
}

extern "C" void kernel_launch(void* const* d_in, const int* in_sizes, int n_in,
                              void* d_out, int out_size) {
    (void)in_sizes; (void)n_in; (void)out_size;
    const float* s = (const float*)d_in[0];
    float* out = (float*)d_out;

    k_max<<<2048, 256>>>(s);
    k_build2<<<dim3(1024, BB), 256>>>(s);
    k_inv0<<<BB, 256>>>();
    k_all<<<NSTEP * 4080, 256>>>();
    k_out2<<<dim3(32, 32, BB), dim3(32, 8)>>>(s, out);
}

// round 15
// speedup vs baseline: 1.0363x; 1.0363x over previous
#include <cuda_runtime.h>
#include <math.h>
#include <stdint.h>

#define BB 16
#define SS 1024
#define NB 64
#define NSTEP 16   // 1024/64

// ---- static device scratch (allocation-free) ----
static __device__ float g_M [(size_t)BB * SS * SS];   // 64 MB: padded minors -> inverses
static __device__ float g_S [(size_t)BB * NB * SS];   // 4 MB: stashed old row stripe
static __device__ float g_P [(size_t)BB * NB * NB];   // 256 KB: current pivot inverse P^-1
static __device__ unsigned long long g_maxkey;        // (sortable-key<<32)|argmax
static __device__ int g_fR[BB * 16];                  // row-panel done flags (stash ready)
static __device__ int g_fC[BB * 16];                  // col-panel done flags (L_new ready)

__device__ __forceinline__ unsigned int enc_f(float v) {
    unsigned int u = __float_as_uint(v);
    return (u & 0x80000000u) ? ~u : (u | 0x80000000u);
}
__device__ __forceinline__ float dec_f(unsigned int k) {
    unsigned int u = (k & 0x80000000u) ? (k ^ 0x80000000u) : ~k;
    return __uint_as_float(u);
}
__device__ __forceinline__ float get_m() { return dec_f((unsigned int)(g_maxkey >> 32)); }

// ---- register Gauss-Jordan inversion of a 64x64 block (8 warps x 8 rows x 2 cols/lane) ----
__device__ __forceinline__ void gj64(float pr[8][2], float (*rowbuf)[64], int w, int l) {
    for (int pw = 0; pw < 8; pw++) {
        #pragma unroll
        for (int rp = 0; rp < 8; rp++) {
            const int p = pw * 8 + rp;
            float* buf = rowbuf[rp & 1];
            if (w == pw) { buf[l] = pr[rp][0]; buf[l + 32] = pr[rp][1]; }
            __syncthreads();
            const float r0 = buf[l], r1 = buf[l + 32];
            const float pinv = 1.0f / buf[p];
            const bool hi = (p >= 32);
            const int pl = p & 31;
            #pragma unroll
            for (int r = 0; r < 8; r++) {
                const float src = hi ? pr[r][1] : pr[r][0];
                const float colv = __shfl_sync(0xffffffffu, src, pl);
                if (r == rp && w == pw) {
                    pr[r][0] = r0 * pinv;
                    pr[r][1] = r1 * pinv;
                    if (l == pl) { if (hi) pr[r][1] = pinv; else pr[r][0] = pinv; }
                } else {
                    const float sc = colv * pinv;
                    pr[r][0] -= sc * r0;
                    pr[r][1] -= sc * r1;
                    if (l == pl) { if (hi) pr[r][1] = -sc; else pr[r][0] = -sc; }
                }
            }
        }
    }
}

// ---------------- global max + argmax (float4 loads) ----------------
__global__ void k_max(const float* __restrict__ s) {
    __shared__ unsigned long long sm[256];
    unsigned long long best = 0ULL;
    const size_t total4 = (size_t)BB * SS * SS / 4;
    for (size_t i = (size_t)blockIdx.x * blockDim.x + threadIdx.x; i < total4;
         i += (size_t)gridDim.x * blockDim.x) {
        const float4 v = *((const float4*)s + i);
        const unsigned int i4 = (unsigned int)(i << 2);
        unsigned long long c0 = ((unsigned long long)enc_f(v.x) << 32) | (i4 + 0);
        unsigned long long c1 = ((unsigned long long)enc_f(v.y) << 32) | (i4 + 1);
        unsigned long long c2 = ((unsigned long long)enc_f(v.z) << 32) | (i4 + 2);
        unsigned long long c3 = ((unsigned long long)enc_f(v.w) << 32) | (i4 + 3);
        if (c1 > c0) c0 = c1;
        if (c3 > c2) c2 = c3;
        if (c2 > c0) c0 = c2;
        if (c0 > best) best = c0;
    }
    sm[threadIdx.x] = best;
    __syncthreads();
    for (int o = 128; o > 0; o >>= 1) {
        if (threadIdx.x < o && sm[threadIdx.x + o] > sm[threadIdx.x]) sm[threadIdx.x] = sm[threadIdx.x + o];
        __syncthreads();
    }
    if (threadIdx.x == 0) atomicMax(&g_maxkey, sm[0]);
}

// ---------------- fused rowsum + build: one block per M row (__expf) ----------------
__global__ void __launch_bounds__(256) k_build2(const float* __restrict__ s) {
    __shared__ float e[1024];
    __shared__ double sd[256];
    const int p = blockIdx.x;            // 0..1023
    const int b = blockIdx.y;
    const int tid = threadIdx.x;
    float* Mrow = g_M + ((size_t)b << 20) + ((size_t)p << 10);

    if (p == 1023) {
        for (int q = tid; q < 1024; q += 256) Mrow[q] = (q == 1023) ? 1.0f : 0.0f;
        return;
    }
    const float m = get_m();
    const float* srow = s + ((size_t)b << 20) + ((size_t)(p + 1) << 10);
    float4 v = *(const float4*)(srow + tid * 4);
    float e0 = __expf(v.x - m), e1 = __expf(v.y - m), e2 = __expf(v.z - m), e3 = __expf(v.w - m);
    e[tid * 4 + 0] = e0; e[tid * 4 + 1] = e1; e[tid * 4 + 2] = e2; e[tid * 4 + 3] = e3;
    sd[tid] = (double)e0 + (double)e1 + (double)e2 + (double)e3;
    __syncthreads();
    for (int o = 128; o > 0; o >>= 1) {
        if (tid < o) sd[tid] += sd[tid + o];
        __syncthreads();
    }
    const double r = sd[0];
    for (int q = tid; q < 1024; q += 256) {
        float out;
        if (q == 1023)      out = 0.0f;
        else if (q == p)    out = (float)(r - (double)e[p + 1]);
        else                out = -e[q + 1];
        Mrow[q] = out;
    }
}

// ---------------- initial pivot inversion + flag reset ----------------
__global__ void __launch_bounds__(256) k_inv0() {
    __shared__ float rowbuf[2][64];
    const int b = blockIdx.x, tid = threadIdx.x;
    const int w = tid >> 5, l = tid & 31;
    if (tid < 16) { g_fR[b * 16 + tid] = 0; g_fC[b * 16 + tid] = 0; }
    float pr[8][2];
    const float* Pg = g_M + ((size_t)b << 20);
    #pragma unroll
    for (int r = 0; r < 8; r++) {
        pr[r][0] = Pg[((size_t)(w * 8 + r) << 10) + l];
        pr[r][1] = Pg[((size_t)(w * 8 + r) << 10) + l + 32];
    }
    gj64(pr, rowbuf, w, l);
    float* Pd = g_P + ((size_t)b << 12);
    #pragma unroll
    for (int r = 0; r < 8; r++) {
        Pd[(w * 8 + r) * NB + l]      = pr[r][0];
        Pd[(w * 8 + r) * NB + l + 32] = pr[r][1];
    }
}

// =====================================================================
// Fused step kernel (R13, banked): 1-D grid of 4080 CTAs, PANELS FIRST
// (bids 0..479, batch-interleaved), then trail (bids 480+). Trail gates
// on its two producing panels; tid0 spins, syncthreads + threadfence
// (CCTL.IVALL) acquire.
// =====================================================================
__global__ void __launch_bounds__(256) k_step(int k) {
    __shared__ float AsT[2][32 * 68];
    __shared__ float Bs [2][32 * 68];
    __shared__ float rowbuf[2][64];
    const int tid = threadIdx.x;
    const int bid = blockIdx.x;

    if (bid < 480) {
        // ================= PANEL ROLE =================
        const int b = bid & 15;
        const int x = bid >> 4;               // 0..29
        const size_t base = (size_t)b << 20;
        const int role = (x < 15) ? 0 : 1;
        const float* Pd = g_P + ((size_t)b << 12);

        const int ai0 = tid >> 3, ac = (tid & 7) << 2;
        const int ai1 = ai0 + 32;
        const int bk0 = tid >> 4, bj = (tid & 15) << 2;
        const int bk1 = bk0 + 16;

        int ib = k, jb = k;
        const float* Ag;
        const float* Bg;
        float* Sg = 0;
        int bstride;
        if (role == 0) {
            jb = x + (x >= k);
            Ag = Pd;
            Bg = g_M + base + (((size_t)k * NB) << 10) + (size_t)jb * NB;
            Sg = g_S + ((size_t)b << 16) + (size_t)jb * NB;
            bstride = 1024;
        } else {
            ib = (x - 15) + ((x - 15) >= k);
            Ag = g_M + base + (((size_t)ib * NB) << 10) + (size_t)k * NB;
            Bg = Pd;
            bstride = NB;
        }
        const int astride = (role == 0) ? NB : 1024;

        float4 A0 = *(const float4*)(Ag + (size_t)ai0 * astride + ac);
        float4 A1 = *(const float4*)(Ag + (size_t)ai1 * astride + ac);
        float4 B0 = *(const float4*)(Bg + (size_t)bk0 * bstride + bj);
        float4 B1 = *(const float4*)(Bg + (size_t)bk1 * bstride + bj);
        AsT[0][(ac + 0) * 68 + ai0] = A0.x; AsT[0][(ac + 1) * 68 + ai0] = A0.y;
        AsT[0][(ac + 2) * 68 + ai0] = A0.z; AsT[0][(ac + 3) * 68 + ai0] = A0.w;
        AsT[0][(ac + 0) * 68 + ai1] = A1.x; AsT[0][(ac + 1) * 68 + ai1] = A1.y;
        AsT[0][(ac + 2) * 68 + ai1] = A1.z; AsT[0][(ac + 3) * 68 + ai1] = A1.w;
        *(float4*)(&Bs[0][bk0 * 68 + bj]) = B0;
        *(float4*)(&Bs[0][bk1 * 68 + bj]) = B1;
        if (role == 0) {
            *(float4*)(Sg + (size_t)bk0 * SS + bj) = B0;
            *(float4*)(Sg + (size_t)bk1 * SS + bj) = B1;
        }
        A0 = *(const float4*)(Ag + (size_t)ai0 * astride + 32 + ac);
        A1 = *(const float4*)(Ag + (size_t)ai1 * astride + 32 + ac);
        B0 = *(const float4*)(Bg + (size_t)(bk0 + 32) * bstride + bj);
        B1 = *(const float4*)(Bg + (size_t)(bk1 + 32) * bstride + bj);
        __syncthreads();

        const int j0 = (tid & 15) * 4;
        const int i0 = (tid >> 4) * 4;
        float acc[4][4] = {};
        #pragma unroll 8
        for (int kk = 0; kk < 32; kk++) {
            const float4 a = *(const float4*)(&AsT[0][kk * 68 + i0]);
            const float4 v = *(const float4*)(&Bs [0][kk * 68 + j0]);
            acc[0][0] += a.x * v.x; acc[0][1] += a.x * v.y; acc[0][2] += a.x * v.z; acc[0][3] += a.x * v.w;
            acc[1][0] += a.y * v.x; acc[1][1] += a.y * v.y; acc[1][2] += a.y * v.z; acc[1][3] += a.y * v.w;
            acc[2][0] += a.z * v.x; acc[2][1] += a.z * v.y; acc[2][2] += a.z * v.z; acc[2][3] += a.z * v.w;
            acc[3][0] += a.w * v.x; acc[3][1] += a.w * v.y; acc[3][2] += a.w * v.z; acc[3][3] += a.w * v.w;
        }
        AsT[1][(ac + 0) * 68 + ai0] = A0.x; AsT[1][(ac + 1) * 68 + ai0] = A0.y;
        AsT[1][(ac + 2) * 68 + ai0] = A0.z; AsT[1][(ac + 3) * 68 + ai0] = A0.w;
        AsT[1][(ac + 0) * 68 + ai1] = A1.x; AsT[1][(ac + 1) * 68 + ai1] = A1.y;
        AsT[1][(ac + 2) * 68 + ai1] = A1.z; AsT[1][(ac + 3) * 68 + ai1] = A1.w;
        *(float4*)(&Bs[1][bk0 * 68 + bj]) = B0;
        *(float4*)(&Bs[1][bk1 * 68 + bj]) = B1;
        if (role == 0) {
            *(float4*)(Sg + (size_t)(bk0 + 32) * SS + bj) = B0;
            *(float4*)(Sg + (size_t)(bk1 + 32) * SS + bj) = B1;
        }
        __syncthreads();
        #pragma unroll 8
        for (int kk = 0; kk < 32; kk++) {
            const float4 a = *(const float4*)(&AsT[1][kk * 68 + i0]);
            const float4 v = *(const float4*)(&Bs [1][kk * 68 + j0]);
            acc[0][0] += a.x * v.x; acc[0][1] += a.x * v.y; acc[0][2] += a.x * v.z; acc[0][3] += a.x * v.w;
            acc[1][0] += a.y * v.x; acc[1][1] += a.y * v.y; acc[1][2] += a.y * v.z; acc[1][3] += a.y * v.w;
            acc[2][0] += a.z * v.x; acc[2][1] += a.z * v.y; acc[2][2] += a.z * v.z; acc[2][3] += a.z * v.w;
            acc[3][0] += a.w * v.x; acc[3][1] += a.w * v.y; acc[3][2] += a.w * v.z; acc[3][3] += a.w * v.w;
        }

        float* Cg = (role == 0)
            ? g_M + base + (((size_t)k  * NB) << 10) + (size_t)jb * NB
            : g_M + base + (((size_t)ib * NB) << 10) + (size_t)k  * NB;
        const float sgn = (role == 0) ? 1.0f : -1.0f;
        #pragma unroll
        for (int r = 0; r < 4; r++) {
            float4 c;
            c.x = sgn * acc[r][0]; c.y = sgn * acc[r][1];
            c.z = sgn * acc[r][2]; c.w = sgn * acc[r][3];
            *(float4*)(Cg + ((size_t)(i0 + r) << 10) + j0) = c;
        }

        // ---- release: stores device-visible, then tag flag ----
        __threadfence();
        __syncthreads();
        if (tid == 0) {
            if (role == 0) atomicExch(&g_fR[b * 16 + jb], k + 1);
            else           atomicExch(&g_fC[b * 16 + ib], k + 1);
        }
        return;
    }

    // ================= TRAIL ROLE =================
    const int t = bid - 480;
    const int b = t & 15;
    const int u = t >> 4;                 // 0..224
    const int ib = (k + 1 + u / 15) & 15;
    const int jb = (k + 1 + u % 15) & 15;
    const bool special = (u == 0);
    const size_t base = (size_t)b << 20;
    const int w = tid >> 5, l = tid & 31;

    if (special) {   // install P^-1(k); nobody reads g_M(k,k) this step
        const float* Pd = g_P + ((size_t)b << 12);
        float* Pg = g_M + base + (((size_t)k * NB) << 10) + (size_t)k * NB;
        #pragma unroll
        for (int f = tid; f < 1024; f += 256) {
            const int r = f >> 4, c4 = (f & 15) << 2;
            *(float4*)(Pg + ((size_t)r << 10) + c4) = *(const float4*)(Pd + r * NB + c4);
        }
    }

    // ---- gate: tid0 spins on the two producing panels ----
    if (tid == 0) {
        volatile int* fR = &g_fR[b * 16 + jb];
        volatile int* fC = &g_fC[b * 16 + ib];
        const int want = k + 1;
        while (*fR < want || *fC < want) __nanosleep(32);
    }
    __syncthreads();
    __threadfence();   // acquire: gpu-scope fence -> CCTL.IVALL flushes stale L1

    const float* Ag = g_M + base + (((size_t)ib * NB) << 10) + (size_t)k * NB;   // L_new(ib,k)
    const float* Bg = g_S + ((size_t)b << 16) + (size_t)jb * NB;                 // stashed old row

    const int ai0 = tid >> 3, ac = (tid & 7) << 2;
    const int ai1 = ai0 + 32;
    const int bk0 = tid >> 4, bj = (tid & 15) << 2;
    const int bk1 = bk0 + 16;

    float4 A0 = *(const float4*)(Ag + ((size_t)ai0 << 10) + ac);
    float4 A1 = *(const float4*)(Ag + ((size_t)ai1 << 10) + ac);
    float4 B0 = *(const float4*)(Bg + (size_t)bk0 * SS + bj);
    float4 B1 = *(const float4*)(Bg + (size_t)bk1 * SS + bj);
    AsT[0][(ac + 0) * 68 + ai0] = A0.x; AsT[0][(ac + 1) * 68 + ai0] = A0.y;
    AsT[0][(ac + 2) * 68 + ai0] = A0.z; AsT[0][(ac + 3) * 68 + ai0] = A0.w;
    AsT[0][(ac + 0) * 68 + ai1] = A1.x; AsT[0][(ac + 1) * 68 + ai1] = A1.y;
    AsT[0][(ac + 2) * 68 + ai1] = A1.z; AsT[0][(ac + 3) * 68 + ai1] = A1.w;
    *(float4*)(&Bs[0][bk0 * 68 + bj]) = B0;
    *(float4*)(&Bs[0][bk1 * 68 + bj]) = B1;
    A0 = *(const float4*)(Ag + ((size_t)ai0 << 10) + 32 + ac);
    A1 = *(const float4*)(Ag + ((size_t)ai1 << 10) + 32 + ac);
    B0 = *(const float4*)(Bg + (size_t)(bk0 + 32) * SS + bj);
    B1 = *(const float4*)(Bg + (size_t)(bk1 + 32) * SS + bj);
    __syncthreads();

    const int j0 = (tid & 15) * 4;
    const int i0 = (tid >> 4) * 4;
    float acc[4][4] = {};
    #pragma unroll 8
    for (int kk = 0; kk < 32; kk++) {
        const float4 a = *(const float4*)(&AsT[0][kk * 68 + i0]);
        const float4 v = *(const float4*)(&Bs [0][kk * 68 + j0]);
        acc[0][0] += a.x * v.x; acc[0][1] += a.x * v.y; acc[0][2] += a.x * v.z; acc[0][3] += a.x * v.w;
        acc[1][0] += a.y * v.x; acc[1][1] += a.y * v.y; acc[1][2] += a.y * v.z; acc[1][3] += a.y * v.w;
        acc[2][0] += a.z * v.x; acc[2][1] += a.z * v.y; acc[2][2] += a.z * v.z; acc[2][3] += a.z * v.w;
        acc[3][0] += a.w * v.x; acc[3][1] += a.w * v.y; acc[3][2] += a.w * v.z; acc[3][3] += a.w * v.w;
    }
    AsT[1][(ac + 0) * 68 + ai0] = A0.x; AsT[1][(ac + 1) * 68 + ai0] = A0.y;
    AsT[1][(ac + 2) * 68 + ai0] = A0.z; AsT[1][(ac + 3) * 68 + ai0] = A0.w;
    AsT[1][(ac + 0) * 68 + ai1] = A1.x; AsT[1][(ac + 1) * 68 + ai1] = A1.y;
    AsT[1][(ac + 2) * 68 + ai1] = A1.z; AsT[1][(ac + 3) * 68 + ai1] = A1.w;
    *(float4*)(&Bs[1][bk0 * 68 + bj]) = B0;
    *(float4*)(&Bs[1][bk1 * 68 + bj]) = B1;
    __syncthreads();
    #pragma unroll 8
    for (int kk = 0; kk < 32; kk++) {
        const float4 a = *(const float4*)(&AsT[1][kk * 68 + i0]);
        const float4 v = *(const float4*)(&Bs [1][kk * 68 + j0]);
        acc[0][0] += a.x * v.x; acc[0][1] += a.x * v.y; acc[0][2] += a.x * v.z; acc[0][3] += a.x * v.w;
        acc[1][0] += a.y * v.x; acc[1][1] += a.y * v.y; acc[1][2] += a.y * v.z; acc[1][3] += a.y * v.w;
        acc[2][0] += a.z * v.x; acc[2][1] += a.z * v.y; acc[2][2] += a.z * v.z; acc[2][3] += a.z * v.w;
        acc[3][0] += a.w * v.x; acc[3][1] += a.w * v.y; acc[3][2] += a.w * v.z; acc[3][3] += a.w * v.w;
    }

    float* Cg = g_M + base + (((size_t)ib * NB) << 10) + (size_t)jb * NB;
    #pragma unroll
    for (int r = 0; r < 4; r++) {
        float4 c = *(float4*)(Cg + ((size_t)(i0 + r) << 10) + j0);
        c.x += acc[r][0]; c.y += acc[r][1]; c.z += acc[r][2]; c.w += acc[r][3];
        *(float4*)(Cg + ((size_t)(i0 + r) << 10) + j0) = c;
    }
    __syncthreads();

    // ---- fused next-pivot inversion: tile (k+1,k+1) just written by this CTA ----
    if (special && k < NSTEP - 1) {
        const int kn = (k + 1) & 15;
        const float* Pg = g_M + base + (((size_t)kn * NB) << 10) + (size_t)kn * NB;
        float pr[8][2];
        #pragma unroll
        for (int r = 0; r < 8; r++) {
            pr[r][0] = Pg[((size_t)(w * 8 + r) << 10) + l];
            pr[r][1] = Pg[((size_t)(w * 8 + r) << 10) + l + 32];
        }
        gj64(pr, rowbuf, w, l);
        float* Pd = g_P + ((size_t)b << 12);
        #pragma unroll
        for (int r = 0; r < 8; r++) {
            Pd[(w * 8 + r) * NB + l]      = pr[r][0];
            Pd[(w * 8 + r) * NB + l + 32] = pr[r][1];
        }
    }
}

// ---------------- assemble probs (fused transpose + diag; __expf) ----------------
__global__ void k_out2(const float* __restrict__ s, float* __restrict__ out) {
    __shared__ float tile[32][33];
    __shared__ float sdiag[32];
    const int b  = blockIdx.z;
    const int p0 = blockIdx.y * 32;
    const int q0 = blockIdx.x * 32;
    const int tx = threadIdx.x, ty = threadIdx.y;   // 32 x 8
    const size_t base = (size_t)b << 20;

    for (int r = ty; r < 32; r += 8) {
        const int q = q0 + r, p = p0 + tx;
        float v = 0.0f;
        if (q >= 1 && p >= 1) v = g_M[base + ((size_t)(q - 1) << 10) + (p - 1)];
        tile[r][tx] = v;
    }
    if (ty == 0) {
        const int p = p0 + tx;
        sdiag[tx] = (p >= 1) ? g_M[base + (size_t)(p - 1) * 1025] : 0.0f;
    }
    __syncthreads();

    const float m = get_m();
    const unsigned long long key = g_maxkey;
    const unsigned int amax = (unsigned int)(key & 0xffffffffu);
    for (int r = ty; r < 32; r += 8) {
        const int p = p0 + r, q = q0 + tx;
        const size_t t = base + ((size_t)p << 10) + q;
        float v = 0.0f;
        if (p >= 1) {
            const float sub = (q >= 1) ? tile[tx][r] : 0.0f;
            v = __expf(s[t] - m) * (sdiag[r] - sub);
        }
        if ((unsigned int)t == amax) v += 16.0f;
        out[t] = v;
    }
}

extern "C" void kernel_launch(void* const* d_in, const int* in_sizes, int n_in,
                              void* d_out, int out_size) {
    (void)in_sizes; (void)n_in; (void)out_size;
    const float* s = (const float*)d_in[0];
    float* out = (float*)d_out;

    k_max<<<2048, 256>>>(s);
    k_build2<<<dim3(1024, BB), 256>>>(s);
    k_inv0<<<BB, 256>>>();

    for (int k = 0; k < NSTEP; k++)
        k_step<<<4080, 256>>>(k);

    k_out2<<<dim3(32, 32, BB), dim3(32, 8)>>>(s, out);
}